// round 12
// baseline (speedup 1.0000x reference)
#include <cuda_runtime.h>
#include <math.h>

#define BB 16
#define SS 2048
#define DD 768
#define BS (BB*SS)
#define OCHUNKS 16
#define OPER (DD/OCHUNKS)   // 48

// ---------------- device scratch (no allocations allowed) ----------------
__device__ float d_part[OCHUNKS][DD*3];  // partial weff sums per o-chunk
__device__ float d_weff[DD*3 + 8];       // [d*3+k]; beff at [DD*3]
__device__ float d_g0[BS];               // G planes (coalesced reads in scan)
__device__ float d_g1[BS];
__device__ float d_g2[BS];
__device__ float d_alpha[BS];
__device__ int   d_tend[BS];
__device__ float d_wbeg[BS + 8];
__device__ float d_wend[BS];
__device__ int   d_nf[BB];

// ---------------- 1a) partial weff: grid (9, 16), coalesced over j ----------------
__global__ void k_weff(const float* __restrict__ conv_w, const float* __restrict__ lin_w) {
    int j = blockIdx.x * 256 + threadIdx.x;          // 0..2303
    if (j >= DD*3) return;
    int o0 = blockIdx.y * OPER;
    float s = 0.f;
    #pragma unroll 8
    for (int oo = 0; oo < OPER; ++oo) {
        int o = o0 + oo;
        s = fmaf(__ldg(&lin_w[o]), conv_w[(size_t)o * (DD*3) + j], s);
    }
    d_part[blockIdx.y][j] = s;
}

// ---------------- 1b) reduce partials (deterministic) + beff ----------------
__global__ void k_weff2(const float* __restrict__ conv_b,
                        const float* __restrict__ lin_w, const float* __restrict__ lin_b) {
    if (blockIdx.x < 9) {
        int j = blockIdx.x * 256 + threadIdx.x;
        if (j < DD*3) {
            float s = 0.f;
            #pragma unroll
            for (int c = 0; c < OCHUNKS; ++c) s += d_part[c][j];
            d_weff[j] = s;
        }
    } else {
        __shared__ float red[256];
        int t = threadIdx.x;
        float s = 0.f;
        for (int o = t; o < DD; o += 256) s = fmaf(lin_w[o], conv_b[o], s);
        red[t] = s;
        __syncthreads();
        for (int off = 128; off; off >>= 1) {
            if (t < off) red[t] += red[t + off];
            __syncthreads();
        }
        if (t == 0) d_weff[DD*3] = red[0] + lin_b[0];
    }
}

// ---------------- 2) G[b,t,k]: one warp per row, float4 ----------------
__global__ void k_g(const float* __restrict__ x) {
    __shared__ float s0[DD], s1[DD], s2[DD];
    for (int i = threadIdx.x; i < DD; i += blockDim.x) {
        s0[i] = d_weff[i*3+0];
        s1[i] = d_weff[i*3+1];
        s2[i] = d_weff[i*3+2];
    }
    __syncthreads();
    int warp = threadIdx.x >> 5, lane = threadIdx.x & 31;
    int row  = blockIdx.x * (blockDim.x >> 5) + warp;    // 0..BS-1
    if (row >= BS) return;
    const float4* xr = (const float4*)(x + (size_t)row * DD);
    const float4* w0 = (const float4*)s0;
    const float4* w1 = (const float4*)s1;
    const float4* w2 = (const float4*)s2;
    float a0 = 0.f, a1 = 0.f, a2 = 0.f;
    #pragma unroll
    for (int i = 0; i < DD/128; ++i) {                   // 6 iterations
        int d4 = lane + i*32;
        float4 v = xr[d4];
        float4 c0 = w0[d4], c1 = w1[d4], c2 = w2[d4];
        a0 = fmaf(v.x, c0.x, fmaf(v.y, c0.y, fmaf(v.z, c0.z, fmaf(v.w, c0.w, a0))));
        a1 = fmaf(v.x, c1.x, fmaf(v.y, c1.y, fmaf(v.z, c1.z, fmaf(v.w, c1.w, a1))));
        a2 = fmaf(v.x, c2.x, fmaf(v.y, c2.y, fmaf(v.z, c2.z, fmaf(v.w, c2.w, a2))));
    }
    #pragma unroll
    for (int o = 16; o; o >>= 1) {
        a0 += __shfl_xor_sync(0xFFFFFFFFu, a0, o);
        a1 += __shfl_xor_sync(0xFFFFFFFFu, a1, o);
        a2 += __shfl_xor_sync(0xFFFFFFFFu, a2, o);
    }
    if (lane == 0) {
        d_g0[row] = a0; d_g1[row] = a1; d_g2[row] = a2;
    }
}

// ---------------- 3) fused alpha + branchless bit-select CIF chain + compaction ------
__global__ void k_scan(const int* __restrict__ lens, float* __restrict__ out_len, int write_len) {
    __shared__ float sa[SS + 8];  // alphas (zero beyond len; +8 pad for lookahead)
    __shared__ float sacc[SS];    // aacc BEFORE each step
    __shared__ int   wsum[8];
    int b   = blockIdx.x;
    int tid = threadIdx.x;
    int base = b * SS;
    int len = lens[b];
    if (len > SS) len = SS;
    if (len < 0)  len = 0;

    // --- staging: alphas from g planes (coalesced); pad sa with 0 (no-op steps) ---
    float beff = d_weff[DD*3];
    #pragma unroll
    for (int i = 0; i < SS/256; ++i) {
        int s = tid + i*256;
        int idx = base + s;
        float pre = beff + d_g1[idx];
        if (s > 0)    pre += d_g0[idx-1];
        if (s < SS-1) pre += d_g2[idx+1];
        float a = 1.f / (1.f + expf(-pre));
        d_alpha[idx] = a;
        sa[s] = (s < len) ? a : 0.f;
    }
    if (tid < 8) sa[SS + tid] = 0.f;
    __syncthreads();

    // --- sequential chain: thread 0, predicate-free (IADD3+SHF mask, LOP3 selects) ---
    // u ∈ (0,2) positive => fire ⇔ bits(u) >= 0x3F800000. Bit-select between the two
    // exact fp32 candidates keeps results bit-identical to the sequential reference.
    if (tid == 0) {
        int nsteps = (len + 7) & ~7;   // zero-padded alphas make tail steps no-ops
        float aacc = 0.f;
        float a_c  = sa[0];
        float u    = aacc + a_c;       // u_0 = RN(0 + a0) = a0, ref-exact
        float a1   = 1.0f - aacc;
        float a2   = a_c - a1;
        for (int c = 0; c < nsteps; c += 8) {
            float nx[8];
            #pragma unroll
            for (int i = 0; i < 8; ++i) nx[i] = sa[c + 1 + i];   // a_{t+1} batch
            #pragma unroll
            for (int i = 0; i < 8; ++i) {
                sacc[c + i] = aacc;
                float an = nx[i];
                int   ui = __float_as_int(u);
                int   m  = (0x3F7FFFFF - ui) >> 31;     // -1 if fire else 0
                float uA = u  + an;                     // next u, no-fire (aacc'=u)
                float uB = a2 + an;                     // next u, fire    (aacc'=a2)
                int aacci = (__float_as_int(a2) & m) | (ui & ~m);
                aacc = __int_as_float(aacci);           // aacc_{t+1}, bit-exact
                int un = (__float_as_int(uB) & m) | (__float_as_int(uA) & ~m);
                u = __int_as_float(un);                 // u_{t+1}, bit-exact
                a1 = 1.0f - aacc;                       // ref op order, step t+1
                a2 = an - a1;
            }
        }
        d_wbeg[base] = 0.f;
    }
    __syncthreads();

    // --- parallel compaction: recompute fires bit-exactly, prefix-scan, write tables ---
    int t0 = tid * 8;
    unsigned f[8];
    int cnt = 0;
    #pragma unroll
    for (int i = 0; i < 8; ++i) {
        int t = t0 + i;
        unsigned fire = 0;
        if (t < len) {
            float ab = sacc[t];
            float a  = sa[t];
            fire = ((ab + a) >= 1.0f) ? 1u : 0u;   // identical RN inputs as chain
        }
        f[i] = fire;
        cnt += (int)fire;
    }
    int lane = tid & 31, w = tid >> 5;
    int inc = cnt;
    #pragma unroll
    for (int o = 1; o < 32; o <<= 1) {
        int v = __shfl_up_sync(0xFFFFFFFFu, inc, o);
        if (lane >= o) inc += v;
    }
    if (lane == 31) wsum[w] = inc;
    __syncthreads();
    int woff = 0;
    #pragma unroll
    for (int i = 0; i < 8; ++i) woff += (i < w) ? wsum[i] : 0;
    int pos = base + woff + inc - cnt;    // exclusive prefix
    #pragma unroll
    for (int i = 0; i < 8; ++i) {
        if (f[i]) {
            int t = t0 + i;
            float ab = sacc[t];
            float a  = sa[t];
            float a1 = 1.0f - ab;
            float a2 = a - a1;
            d_tend[pos] = t;
            d_wend[pos] = a1;
            d_wbeg[pos + 1] = a2;
            pos++;
        }
    }
    if (tid == 255) {
        int total = woff + inc;
        d_nf[b] = total;
        if (write_len) out_len[b] = (float)total;
    }
}

// ---------------- 4) emit: segmented weighted sum, float4, 192 thr/block ----------------
__global__ void k_emit(const float* __restrict__ x, float* __restrict__ out) {
    int r = blockIdx.x, b = blockIdx.y;
    int tid = threadIdx.x;
    float4* orow = (float4*)(out + ((size_t)b*SS + r) * DD);
    int nf = d_nf[b];
    if (r >= nf) {
        orow[tid] = make_float4(0.f, 0.f, 0.f, 0.f);
        return;
    }
    int base = b*SS;
    int t1 = d_tend[base + r];
    int t0 = (r == 0) ? -1 : d_tend[base + r - 1];
    const float4* xb = (const float4*)(x + (size_t)b*SS*DD);
    float4 acc = make_float4(0.f, 0.f, 0.f, 0.f);
    if (r > 0) {
        float w = d_wbeg[base + r];
        float4 v = xb[(size_t)t0 * (DD/4) + tid];
        acc.x = w*v.x; acc.y = w*v.y; acc.z = w*v.z; acc.w = w*v.w;
    }
    for (int t = t0 + 1; t < t1; ++t) {
        float w = d_alpha[base + t];
        float4 v = xb[(size_t)t * (DD/4) + tid];
        acc.x = fmaf(w, v.x, acc.x); acc.y = fmaf(w, v.y, acc.y);
        acc.z = fmaf(w, v.z, acc.z); acc.w = fmaf(w, v.w, acc.w);
    }
    {
        float w = d_wend[base + r];
        float4 v = xb[(size_t)t1 * (DD/4) + tid];
        acc.x = fmaf(w, v.x, acc.x); acc.y = fmaf(w, v.y, acc.y);
        acc.z = fmaf(w, v.z, acc.z); acc.w = fmaf(w, v.w, acc.w);
    }
    orow[tid] = acc;
}

extern "C" void kernel_launch(void* const* d_in, const int* in_sizes, int n_in,
                              void* d_out, int out_size) {
    const float* x      = (const float*)d_in[0];   // (B,S,D) f32
    const int*   lens   = (const int*)  d_in[1];   // (B,) i32
    const float* conv_w = (const float*)d_in[2];   // (D,D,3)
    const float* conv_b = (const float*)d_in[3];   // (D,)
    const float* lin_w  = (const float*)d_in[4];   // (1,D)
    const float* lin_b  = (const float*)d_in[5];   // (1,)
    float* out = (float*)d_out;

    const int BSD = BB * SS * DD;
    int write_len = (out_size >= BSD + BB) ? 1 : 0;

    k_weff <<<dim3(9, OCHUNKS), 256>>>(conv_w, lin_w);
    k_weff2<<<10, 256>>>(conv_b, lin_w, lin_b);
    k_g    <<<BS / 8, 256>>>(x);
    k_scan <<<BB, 256>>>(lens, out + BSD, write_len);
    k_emit <<<dim3(SS, BB), 192>>>(x, out);
}

// round 14
// speedup vs baseline: 1.0372x; 1.0372x over previous
#include <cuda_runtime.h>
#include <math.h>

#define BB 16
#define SS 2048
#define DD 768
#define BS (BB*SS)
#define OCHUNKS 16
#define OPER (DD/OCHUNKS)   // 48

// ---------------- device scratch (no allocations allowed) ----------------
__device__ float d_part[OCHUNKS][DD*3];  // partial weff sums per o-chunk
__device__ float d_weff[DD*3 + 8];       // [d*3+k]; beff at [DD*3]
__device__ float d_g0[BS];               // G planes (coalesced reads in scan)
__device__ float d_g1[BS];
__device__ float d_g2[BS];
__device__ float d_alpha[BS];
__device__ int   d_tend[BS];
__device__ float d_wbeg[BS + 8];
__device__ float d_wend[BS];
__device__ int   d_nf[BB];

// ---------------- 1a) partial weff: grid (9, 16), coalesced over j ----------------
__global__ void k_weff(const float* __restrict__ conv_w, const float* __restrict__ lin_w) {
    int j = blockIdx.x * 256 + threadIdx.x;          // 0..2303
    if (j >= DD*3) return;
    int o0 = blockIdx.y * OPER;
    float s = 0.f;
    #pragma unroll 8
    for (int oo = 0; oo < OPER; ++oo) {
        int o = o0 + oo;
        s = fmaf(__ldg(&lin_w[o]), conv_w[(size_t)o * (DD*3) + j], s);
    }
    d_part[blockIdx.y][j] = s;
}

// ---------------- 1b) reduce partials (deterministic) + beff ----------------
__global__ void k_weff2(const float* __restrict__ conv_b,
                        const float* __restrict__ lin_w, const float* __restrict__ lin_b) {
    if (blockIdx.x < 9) {
        int j = blockIdx.x * 256 + threadIdx.x;
        if (j < DD*3) {
            float s = 0.f;
            #pragma unroll
            for (int c = 0; c < OCHUNKS; ++c) s += d_part[c][j];
            d_weff[j] = s;
        }
    } else {
        __shared__ float red[256];
        int t = threadIdx.x;
        float s = 0.f;
        for (int o = t; o < DD; o += 256) s = fmaf(lin_w[o], conv_b[o], s);
        red[t] = s;
        __syncthreads();
        for (int off = 128; off; off >>= 1) {
            if (t < off) red[t] += red[t + off];
            __syncthreads();
        }
        if (t == 0) d_weff[DD*3] = red[0] + lin_b[0];
    }
}

// ---------------- 2) G[b,t,k]: one warp per row, float4 ----------------
__global__ void k_g(const float* __restrict__ x) {
    __shared__ float s0[DD], s1[DD], s2[DD];
    for (int i = threadIdx.x; i < DD; i += blockDim.x) {
        s0[i] = d_weff[i*3+0];
        s1[i] = d_weff[i*3+1];
        s2[i] = d_weff[i*3+2];
    }
    __syncthreads();
    int warp = threadIdx.x >> 5, lane = threadIdx.x & 31;
    int row  = blockIdx.x * (blockDim.x >> 5) + warp;    // 0..BS-1
    if (row >= BS) return;
    const float4* xr = (const float4*)(x + (size_t)row * DD);
    const float4* w0 = (const float4*)s0;
    const float4* w1 = (const float4*)s1;
    const float4* w2 = (const float4*)s2;
    float a0 = 0.f, a1 = 0.f, a2 = 0.f;
    #pragma unroll
    for (int i = 0; i < DD/128; ++i) {                   // 6 iterations
        int d4 = lane + i*32;
        float4 v = xr[d4];
        float4 c0 = w0[d4], c1 = w1[d4], c2 = w2[d4];
        a0 = fmaf(v.x, c0.x, fmaf(v.y, c0.y, fmaf(v.z, c0.z, fmaf(v.w, c0.w, a0))));
        a1 = fmaf(v.x, c1.x, fmaf(v.y, c1.y, fmaf(v.z, c1.z, fmaf(v.w, c1.w, a1))));
        a2 = fmaf(v.x, c2.x, fmaf(v.y, c2.y, fmaf(v.z, c2.z, fmaf(v.w, c2.w, a2))));
    }
    #pragma unroll
    for (int o = 16; o; o >>= 1) {
        a0 += __shfl_xor_sync(0xFFFFFFFFu, a0, o);
        a1 += __shfl_xor_sync(0xFFFFFFFFu, a1, o);
        a2 += __shfl_xor_sync(0xFFFFFFFFu, a2, o);
    }
    if (lane == 0) {
        d_g0[row] = a0; d_g1[row] = a1; d_g2[row] = a2;
    }
}

// ---------------- 3) fused alpha + pipelined CIF chain (selp) + compaction ----------
__global__ void k_scan(const int* __restrict__ lens, float* __restrict__ out_len, int write_len) {
    __shared__ float sa[SS + 8];  // alphas (zero beyond len)
    __shared__ float sacc[SS];    // aacc BEFORE each step
    __shared__ int   wsum[8];
    int b   = blockIdx.x;
    int tid = threadIdx.x;
    int base = b * SS;
    int len = lens[b];
    if (len > SS) len = SS;
    if (len < 0)  len = 0;

    // --- staging: alphas from g planes (coalesced); pad sa with 0 (no-op steps) ---
    float beff = d_weff[DD*3];
    #pragma unroll
    for (int i = 0; i < SS/256; ++i) {
        int s = tid + i*256;
        int idx = base + s;
        float pre = beff + d_g1[idx];
        if (s > 0)    pre += d_g0[idx-1];
        if (s < SS-1) pre += d_g2[idx+1];
        float a = 1.f / (1.f + expf(-pre));
        d_alpha[idx] = a;
        sa[s] = (s < len) ? a : 0.f;
    }
    if (tid < 8) sa[SS + tid] = 0.f;
    __syncthreads();

    // --- sequential chain: thread 0, register-prefetch pipeline, forced selp.f32 ---
    if (tid == 0) {
        float aacc = 0.f;
        int nsteps = (len + 7) & ~7;          // zero-padded tail steps are no-ops
        float cur[8];
        #pragma unroll
        for (int i = 0; i < 8; ++i) cur[i] = sa[i];
        for (int c = 0; c < nsteps; c += 8) {
            float nxt[8];
            int cn = (c + 8) & (SS - 1);
            #pragma unroll
            for (int i = 0; i < 8; ++i) nxt[i] = sa[cn + i];
            #pragma unroll
            for (int i = 0; i < 8; ++i) {
                sacc[c + i] = aacc;
                float a  = cur[i];
                float u  = aacc + a;          // exact ref op order
                float a1 = 1.0f - aacc;
                float a2 = a - a1;
                // aacc = (u >= 1.0f) ? a2 : u;  -- force FSETP+FSEL (pred-as-data)
                asm("{\n\t"
                    ".reg .pred p;\n\t"
                    "setp.ge.f32 p, %1, 0f3F800000;\n\t"
                    "selp.f32 %0, %2, %3, p;\n\t"
                    "}" : "=f"(aacc) : "f"(u), "f"(a2), "f"(u));
            }
            #pragma unroll
            for (int i = 0; i < 8; ++i) cur[i] = nxt[i];
        }
        d_wbeg[base] = 0.f;
    }
    __syncthreads();

    // --- parallel compaction: recompute fires bit-exactly, prefix-scan, write tables ---
    int t0 = tid * 8;
    unsigned f[8];
    int cnt = 0;
    #pragma unroll
    for (int i = 0; i < 8; ++i) {
        int t = t0 + i;
        unsigned fire = 0;
        if (t < len) {
            float ab = sacc[t];
            float a  = sa[t];
            fire = ((ab + a) >= 1.0f) ? 1u : 0u;   // identical RN inputs as chain
        }
        f[i] = fire;
        cnt += (int)fire;
    }
    int lane = tid & 31, w = tid >> 5;
    int inc = cnt;
    #pragma unroll
    for (int o = 1; o < 32; o <<= 1) {
        int v = __shfl_up_sync(0xFFFFFFFFu, inc, o);
        if (lane >= o) inc += v;
    }
    if (lane == 31) wsum[w] = inc;
    __syncthreads();
    int woff = 0;
    #pragma unroll
    for (int i = 0; i < 8; ++i) woff += (i < w) ? wsum[i] : 0;
    int pos = base + woff + inc - cnt;    // exclusive prefix
    #pragma unroll
    for (int i = 0; i < 8; ++i) {
        if (f[i]) {
            int t = t0 + i;
            float ab = sacc[t];
            float a  = sa[t];
            float a1 = 1.0f - ab;
            float a2 = a - a1;
            d_tend[pos] = t;
            d_wend[pos] = a1;
            d_wbeg[pos + 1] = a2;
            pos++;
        }
    }
    if (tid == 255) {
        int total = woff + inc;
        d_nf[b] = total;
        if (write_len) out_len[b] = (float)total;
    }
}

// ---------------- 4) emit: 4 rows per block, boundary-row register reuse ------------
#define EM_ACC(ACC, W, V) do { ACC.x = fmaf(W, V.x, ACC.x); ACC.y = fmaf(W, V.y, ACC.y); \
                               ACC.z = fmaf(W, V.z, ACC.z); ACC.w = fmaf(W, V.w, ACC.w); } while(0)

__global__ void k_emit(const float* __restrict__ x, float* __restrict__ out) {
    int r0 = blockIdx.x * 4, b = blockIdx.y;
    int tid = threadIdx.x;                               // 192 threads, one float4 each
    int base = b * SS;
    int nf = d_nf[b];
    float4* ob = (float4*)(out + ((size_t)base) * DD);
    const float4 z = make_float4(0.f, 0.f, 0.f, 0.f);
    int nreal = nf - r0;
    if (nreal > 4) nreal = 4;
    if (nreal <= 0) {
        #pragma unroll
        for (int i = 0; i < 4; ++i) ob[(size_t)(r0 + i) * (DD/4) + tid] = z;
        return;
    }
    const float4* xb = (const float4*)(x + (size_t)base * DD);
    const float*  al = d_alpha + base;
    float4 acc0 = z, acc1 = z, acc2 = z, acc3 = z;
    float4 v;
    int t = (r0 == 0) ? 0 : d_tend[base + r0 - 1];

    // row 0 of block
    {
        int hi = d_tend[base + r0];
        if (r0 > 0) {                          // boundary from previous block's fire
            v = xb[(size_t)t * (DD/4) + tid];
            float w = d_wbeg[base + r0];
            EM_ACC(acc0, w, v);
            ++t;
        }
        for (; t < hi; ++t) {
            v = xb[(size_t)t * (DD/4) + tid];
            EM_ACC(acc0, al[t], v);
        }
        v = xb[(size_t)hi * (DD/4) + tid];
        float w = d_wend[base + r0];
        EM_ACC(acc0, w, v);
        t = hi + 1;
    }
    if (nreal >= 2) {                          // v currently = x[tend[r0]]
        int hi = d_tend[base + r0 + 1];
        float wb = d_wbeg[base + r0 + 1];
        EM_ACC(acc1, wb, v);
        for (; t < hi; ++t) {
            v = xb[(size_t)t * (DD/4) + tid];
            EM_ACC(acc1, al[t], v);
        }
        v = xb[(size_t)hi * (DD/4) + tid];
        float w = d_wend[base + r0 + 1];
        EM_ACC(acc1, w, v);
        t = hi + 1;
    }
    if (nreal >= 3) {
        int hi = d_tend[base + r0 + 2];
        float wb = d_wbeg[base + r0 + 2];
        EM_ACC(acc2, wb, v);
        for (; t < hi; ++t) {
            v = xb[(size_t)t * (DD/4) + tid];
            EM_ACC(acc2, al[t], v);
        }
        v = xb[(size_t)hi * (DD/4) + tid];
        float w = d_wend[base + r0 + 2];
        EM_ACC(acc2, w, v);
        t = hi + 1;
    }
    if (nreal >= 4) {
        int hi = d_tend[base + r0 + 3];
        float wb = d_wbeg[base + r0 + 3];
        EM_ACC(acc3, wb, v);
        for (; t < hi; ++t) {
            v = xb[(size_t)t * (DD/4) + tid];
            EM_ACC(acc3, al[t], v);
        }
        v = xb[(size_t)hi * (DD/4) + tid];
        float w = d_wend[base + r0 + 3];
        EM_ACC(acc3, w, v);
    }
    ob[(size_t)(r0 + 0) * (DD/4) + tid] = acc0;
    ob[(size_t)(r0 + 1) * (DD/4) + tid] = acc1;
    ob[(size_t)(r0 + 2) * (DD/4) + tid] = acc2;
    ob[(size_t)(r0 + 3) * (DD/4) + tid] = acc3;
}

extern "C" void kernel_launch(void* const* d_in, const int* in_sizes, int n_in,
                              void* d_out, int out_size) {
    const float* x      = (const float*)d_in[0];   // (B,S,D) f32
    const int*   lens   = (const int*)  d_in[1];   // (B,) i32
    const float* conv_w = (const float*)d_in[2];   // (D,D,3)
    const float* conv_b = (const float*)d_in[3];   // (D,)
    const float* lin_w  = (const float*)d_in[4];   // (1,D)
    const float* lin_b  = (const float*)d_in[5];   // (1,)
    float* out = (float*)d_out;

    const int BSD = BB * SS * DD;
    int write_len = (out_size >= BSD + BB) ? 1 : 0;

    k_weff <<<dim3(9, OCHUNKS), 256>>>(conv_w, lin_w);
    k_weff2<<<10, 256>>>(conv_b, lin_w, lin_b);
    k_g    <<<BS / 8, 256>>>(x);
    k_scan <<<BB, 256>>>(lens, out + BSD, write_len);
    k_emit <<<dim3(SS/4, BB), 192>>>(x, out);
}

// round 15
// speedup vs baseline: 1.1375x; 1.0967x over previous
#include <cuda_runtime.h>
#include <math.h>

#define BB 16
#define SS 2048
#define DD 768
#define BS (BB*SS)
#define OCHUNKS 16
#define OPER (DD/OCHUNKS)   // 48

#define NSCAN  BB            // 16 scan blocks (first: wave-1 residency)
#define NG     4096          // g blocks: 256 per batch, 8 rows each
#define NEMIT  8192          // emit blocks: 512 per batch, 4 rows each
#define GPERB  (NG/BB)       // 256
#define EPERB  (NEMIT/BB)    // 512

// ---------------- device scratch (no allocations allowed) ----------------
__device__ float d_part[OCHUNKS][DD*3];
__device__ float d_weff[DD*3 + 8];       // [d*3+k]; beff at [DD*3]
__device__ float d_g0[BS];
__device__ float d_g1[BS];
__device__ float d_g2[BS];
__device__ float d_alpha[BS];
__device__ int   d_tend[BS];
__device__ float d_wbeg[BS + 8];
__device__ float d_wend[BS];
__device__ int   d_nf[BB];
__device__ int   d_cnt[BB];              // g-blocks completed per batch
__device__ int   d_flag[BB];             // scan done per batch

// ---------------- 1a) partial weff ----------------
__global__ void k_weff(const float* __restrict__ conv_w, const float* __restrict__ lin_w) {
    int j = blockIdx.x * 256 + threadIdx.x;
    if (j >= DD*3) return;
    int o0 = blockIdx.y * OPER;
    float s = 0.f;
    #pragma unroll 8
    for (int oo = 0; oo < OPER; ++oo) {
        int o = o0 + oo;
        s = fmaf(__ldg(&lin_w[o]), conv_w[(size_t)o * (DD*3) + j], s);
    }
    d_part[blockIdx.y][j] = s;
}

// ---------------- 1b) reduce partials + beff + reset pipeline flags ----------------
__global__ void k_weff2(const float* __restrict__ conv_b,
                        const float* __restrict__ lin_w, const float* __restrict__ lin_b) {
    if (blockIdx.x == 0 && threadIdx.x < BB) {       // reset per-replay (stream-ordered)
        d_cnt[threadIdx.x] = 0;
        d_flag[threadIdx.x] = 0;
    }
    if (blockIdx.x < 9) {
        int j = blockIdx.x * 256 + threadIdx.x;
        if (j < DD*3) {
            float s = 0.f;
            #pragma unroll
            for (int c = 0; c < OCHUNKS; ++c) s += d_part[c][j];
            d_weff[j] = s;
        }
    } else {
        __shared__ float red[256];
        int t = threadIdx.x;
        float s = 0.f;
        for (int o = t; o < DD; o += 256) s = fmaf(lin_w[o], conv_b[o], s);
        red[t] = s;
        __syncthreads();
        for (int off = 128; off; off >>= 1) {
            if (t < off) red[t] += red[t + off];
            __syncthreads();
        }
        if (t == 0) d_weff[DD*3] = red[0] + lin_b[0];
    }
}

// ---------------- fused pipeline: g -> scan -> emit, flag-synced per batch ----------
#define EM_ACC(ACC, W, V) do { ACC.x = fmaf(W, V.x, ACC.x); ACC.y = fmaf(W, V.y, ACC.y); \
                               ACC.z = fmaf(W, V.z, ACC.z); ACC.w = fmaf(W, V.w, ACC.w); } while(0)

__global__ __launch_bounds__(256) void k_fused(const float* __restrict__ x,
                                               const int* __restrict__ lens,
                                               float* __restrict__ out,
                                               float* __restrict__ out_len, int write_len) {
    __shared__ __align__(16) char smem_buf[(SS + 8 + SS) * 4 + 64];
    int bid = blockIdx.x;
    int tid = threadIdx.x;

    if (bid < NSCAN) {
        // ============ SCAN role (batch = bid) ============
        float* sa   = (float*)smem_buf;          // [SS+8]
        float* sacc = sa + SS + 8;               // [SS]
        int*   wsum = (int*)(sacc + SS);         // [8]
        int b = bid;
        int base = b * SS;
        int len = lens[b];
        if (len > SS) len = SS;
        if (len < 0)  len = 0;

        // wait for this batch's g blocks
        if (tid == 0) {
            while (atomicAdd(&d_cnt[b], 0) < GPERB) __nanosleep(100);
        }
        __syncthreads();
        __threadfence();

        // staging: alphas from g planes; zero-pad beyond len
        float beff = d_weff[DD*3];
        #pragma unroll
        for (int i = 0; i < SS/256; ++i) {
            int s = tid + i*256;
            int idx = base + s;
            float pre = beff + d_g1[idx];
            if (s > 0)    pre += d_g0[idx-1];
            if (s < SS-1) pre += d_g2[idx+1];
            float a = 1.f / (1.f + expf(-pre));
            d_alpha[idx] = a;
            sa[s] = (s < len) ? a : 0.f;
        }
        if (tid < 8) sa[SS + tid] = 0.f;
        __syncthreads();

        // sequential chain: thread 0, register-prefetch pipeline, forced selp.f32
        if (tid == 0) {
            float aacc = 0.f;
            int nsteps = (len + 7) & ~7;
            float cur[8];
            #pragma unroll
            for (int i = 0; i < 8; ++i) cur[i] = sa[i];
            for (int c = 0; c < nsteps; c += 8) {
                float nxt[8];
                int cn = (c + 8) & (SS - 1);
                #pragma unroll
                for (int i = 0; i < 8; ++i) nxt[i] = sa[cn + i];
                #pragma unroll
                for (int i = 0; i < 8; ++i) {
                    sacc[c + i] = aacc;
                    float a  = cur[i];
                    float u  = aacc + a;          // exact ref op order
                    float a1 = 1.0f - aacc;
                    float a2 = a - a1;
                    asm("{\n\t"
                        ".reg .pred p;\n\t"
                        "setp.ge.f32 p, %1, 0f3F800000;\n\t"
                        "selp.f32 %0, %2, %3, p;\n\t"
                        "}" : "=f"(aacc) : "f"(u), "f"(a2), "f"(u));
                }
                #pragma unroll
                for (int i = 0; i < 8; ++i) cur[i] = nxt[i];
            }
            d_wbeg[base] = 0.f;
        }
        __syncthreads();

        // parallel compaction (bit-exact fire recompute)
        int t0 = tid * 8;
        unsigned f[8];
        int cnt = 0;
        #pragma unroll
        for (int i = 0; i < 8; ++i) {
            int t = t0 + i;
            unsigned fire = 0;
            if (t < len) {
                float ab = sacc[t];
                float a  = sa[t];
                fire = ((ab + a) >= 1.0f) ? 1u : 0u;
            }
            f[i] = fire;
            cnt += (int)fire;
        }
        int lane = tid & 31, w = tid >> 5;
        int inc = cnt;
        #pragma unroll
        for (int o = 1; o < 32; o <<= 1) {
            int v = __shfl_up_sync(0xFFFFFFFFu, inc, o);
            if (lane >= o) inc += v;
        }
        if (lane == 31) wsum[w] = inc;
        __syncthreads();
        int woff = 0;
        #pragma unroll
        for (int i = 0; i < 8; ++i) woff += (i < w) ? wsum[i] : 0;
        int pos = base + woff + inc - cnt;
        #pragma unroll
        for (int i = 0; i < 8; ++i) {
            if (f[i]) {
                int t = t0 + i;
                float ab = sacc[t];
                float a  = sa[t];
                float a1 = 1.0f - ab;
                float a2 = a - a1;
                d_tend[pos] = t;
                d_wend[pos] = a1;
                d_wbeg[pos + 1] = a2;
                pos++;
            }
        }
        if (tid == 255) {
            int total = woff + inc;
            d_nf[b] = total;
            if (write_len) out_len[b] = (float)total;
        }
        __threadfence();
        __syncthreads();
        if (tid == 0) atomicExch(&d_flag[b], 1);   // release tables + alphas

    } else if (bid < NSCAN + NG) {
        // ============ G role: 8 rows (one per warp), batch-ordered ============
        float* s0 = (float*)smem_buf;
        float* s1 = s0 + DD;
        float* s2 = s1 + DD;
        int gb = bid - NSCAN;
        int batch = gb / GPERB;                       // batch-major ordering
        int chunk = gb % GPERB;
        for (int i = tid; i < DD; i += 256) {
            s0[i] = d_weff[i*3+0];
            s1[i] = d_weff[i*3+1];
            s2[i] = d_weff[i*3+2];
        }
        __syncthreads();
        int warp = tid >> 5, lane = tid & 31;
        int row = batch * SS + chunk * 8 + warp;
        const float4* xr = (const float4*)(x + (size_t)row * DD);
        const float4* w0 = (const float4*)s0;
        const float4* w1 = (const float4*)s1;
        const float4* w2 = (const float4*)s2;
        float a0 = 0.f, a1 = 0.f, a2 = 0.f;
        #pragma unroll
        for (int i = 0; i < DD/128; ++i) {
            int d4 = lane + i*32;
            float4 v = xr[d4];
            float4 c0 = w0[d4], c1 = w1[d4], c2 = w2[d4];
            a0 = fmaf(v.x, c0.x, fmaf(v.y, c0.y, fmaf(v.z, c0.z, fmaf(v.w, c0.w, a0))));
            a1 = fmaf(v.x, c1.x, fmaf(v.y, c1.y, fmaf(v.z, c1.z, fmaf(v.w, c1.w, a1))));
            a2 = fmaf(v.x, c2.x, fmaf(v.y, c2.y, fmaf(v.z, c2.z, fmaf(v.w, c2.w, a2))));
        }
        #pragma unroll
        for (int o = 16; o; o >>= 1) {
            a0 += __shfl_xor_sync(0xFFFFFFFFu, a0, o);
            a1 += __shfl_xor_sync(0xFFFFFFFFu, a1, o);
            a2 += __shfl_xor_sync(0xFFFFFFFFu, a2, o);
        }
        if (lane == 0) {
            d_g0[row] = a0; d_g1[row] = a1; d_g2[row] = a2;
        }
        __threadfence();
        __syncthreads();
        if (tid == 0) atomicAdd(&d_cnt[batch], 1);

    } else {
        // ============ EMIT role: 4 rows per block ============
        int eb = bid - NSCAN - NG;
        int b  = eb / EPERB;
        int r0 = (eb % EPERB) * 4;
        if (tid == 0) {
            while (atomicAdd(&d_flag[b], 0) == 0) __nanosleep(100);
        }
        __syncthreads();
        __threadfence();
        if (tid >= 192) return;                       // 192 float4 lanes per row

        int base = b * SS;
        int nf = d_nf[b];
        float4* ob = (float4*)(out + (size_t)base * DD);
        const float4 z = make_float4(0.f, 0.f, 0.f, 0.f);
        int nreal = nf - r0;
        if (nreal > 4) nreal = 4;
        if (nreal <= 0) {
            #pragma unroll
            for (int i = 0; i < 4; ++i) ob[(size_t)(r0 + i) * (DD/4) + tid] = z;
            return;
        }
        const float4* xb = (const float4*)(x + (size_t)base * DD);
        const float*  al = d_alpha + base;
        float4 acc0 = z, acc1 = z, acc2 = z, acc3 = z;
        float4 v;
        int t = (r0 == 0) ? 0 : d_tend[base + r0 - 1];
        {
            int hi = d_tend[base + r0];
            if (r0 > 0) {
                v = xb[(size_t)t * (DD/4) + tid];
                float w = d_wbeg[base + r0];
                EM_ACC(acc0, w, v);
                ++t;
            }
            for (; t < hi; ++t) {
                v = xb[(size_t)t * (DD/4) + tid];
                EM_ACC(acc0, al[t], v);
            }
            v = xb[(size_t)hi * (DD/4) + tid];
            float w = d_wend[base + r0];
            EM_ACC(acc0, w, v);
            t = hi + 1;
        }
        if (nreal >= 2) {
            int hi = d_tend[base + r0 + 1];
            float wb = d_wbeg[base + r0 + 1];
            EM_ACC(acc1, wb, v);
            for (; t < hi; ++t) {
                v = xb[(size_t)t * (DD/4) + tid];
                EM_ACC(acc1, al[t], v);
            }
            v = xb[(size_t)hi * (DD/4) + tid];
            float w = d_wend[base + r0 + 1];
            EM_ACC(acc1, w, v);
            t = hi + 1;
        }
        if (nreal >= 3) {
            int hi = d_tend[base + r0 + 2];
            float wb = d_wbeg[base + r0 + 2];
            EM_ACC(acc2, wb, v);
            for (; t < hi; ++t) {
                v = xb[(size_t)t * (DD/4) + tid];
                EM_ACC(acc2, al[t], v);
            }
            v = xb[(size_t)hi * (DD/4) + tid];
            float w = d_wend[base + r0 + 2];
            EM_ACC(acc2, w, v);
            t = hi + 1;
        }
        if (nreal >= 4) {
            int hi = d_tend[base + r0 + 3];
            float wb = d_wbeg[base + r0 + 3];
            EM_ACC(acc3, wb, v);
            for (; t < hi; ++t) {
                v = xb[(size_t)t * (DD/4) + tid];
                EM_ACC(acc3, al[t], v);
            }
            v = xb[(size_t)hi * (DD/4) + tid];
            float w = d_wend[base + r0 + 3];
            EM_ACC(acc3, w, v);
        }
        ob[(size_t)(r0 + 0) * (DD/4) + tid] = acc0;
        ob[(size_t)(r0 + 1) * (DD/4) + tid] = acc1;
        ob[(size_t)(r0 + 2) * (DD/4) + tid] = acc2;
        ob[(size_t)(r0 + 3) * (DD/4) + tid] = acc3;
    }
}

extern "C" void kernel_launch(void* const* d_in, const int* in_sizes, int n_in,
                              void* d_out, int out_size) {
    const float* x      = (const float*)d_in[0];   // (B,S,D) f32
    const int*   lens   = (const int*)  d_in[1];   // (B,) i32
    const float* conv_w = (const float*)d_in[2];   // (D,D,3)
    const float* conv_b = (const float*)d_in[3];   // (D,)
    const float* lin_w  = (const float*)d_in[4];   // (1,D)
    const float* lin_b  = (const float*)d_in[5];   // (1,)
    float* out = (float*)d_out;

    const int BSD = BB * SS * DD;
    int write_len = (out_size >= BSD + BB) ? 1 : 0;

    k_weff <<<dim3(9, OCHUNKS), 256>>>(conv_w, lin_w);
    k_weff2<<<10, 256>>>(conv_b, lin_w, lin_b);
    k_fused<<<NSCAN + NG + NEMIT, 256>>>(x, lens, out, out + BSD, write_len);
}